// round 2
// baseline (speedup 1.0000x reference)
#include <cuda_runtime.h>

#define KDIM 32
#define CELLS (KDIM * KDIM)
#define NTHREADS 128

__device__ __forceinline__ float ex2_approx(float x) {
    float r;
    asm("ex2.approx.ftz.f32 %0, %1;" : "=f"(r) : "f"(x));
    return r;
}

__global__ __launch_bounds__(NTHREADS)
void ttg2d_kernel(const float* __restrict__ X,
                  const float* __restrict__ Wk0,
                  const float* __restrict__ Wk1k0,
                  const float* __restrict__ Wk2k1,
                  const float* __restrict__ mu,
                  const float* __restrict__ sigma,
                  float* __restrict__ out,
                  int N)
{
    // Packed per-cell coefficients: {mu, a2, C1, D}
    //   a2 = -0.5 * log2(e) / sigma^2          (exponent in base-2)
    //   C1 = Wk2k1 * (1/(sigma*sqrt(2pi)))     (stage-1 weight, cell = [k2][k1])
    //   D  = Wk1k0 * Wk0[k0] * (1/(sigma*sqrt(2pi)))  (stage-2 weight, cell = [k1][k0])
    __shared__ float4 Q[CELLS];

    const float LOG2E        = 1.4426950408889634f;
    const float INV_SQRT_2PI = 0.3989422804014327f;

    for (int i = threadIdx.x; i < CELLS; i += NTHREADS) {
        int c = i & (KDIM - 1);
        float s     = sigma[i];
        float m     = mu[i];
        float inv_s = __fdividef(1.0f, s);
        float a2    = -0.5f * LOG2E * inv_s * inv_s;
        float base  = INV_SQRT_2PI * inv_s;
        float C1    = Wk2k1[i] * base;
        float D     = Wk1k0[i] * base * Wk0[c];
        Q[i] = make_float4(m, a2, C1, D);
    }
    __syncthreads();

    int n = blockIdx.x * NTHREADS + threadIdx.x;
    if (n >= N) return;

    float2 x = reinterpret_cast<const float2*>(X)[n];  // x.x = X[n,0], x.y = X[n,1]

    float acc = 0.0f;

    #pragma unroll 1
    for (int k1 = 0; k1 < KDIM; ++k1) {
        // inner[k1] = sum_k2 C1[k2,k1] * pdf(x1; cell[k2,k1])   (column walk)
        float in0 = 0.0f, in1 = 0.0f;
        #pragma unroll
        for (int k2 = 0; k2 < KDIM; k2 += 2) {
            float4 qa = Q[k2 * KDIM + k1];
            float4 qb = Q[(k2 + 1) * KDIM + k1];
            float da = x.y - qa.x;
            float db = x.y - qb.x;
            float ea = (qa.y * da) * da;
            float eb = (qb.y * db) * db;
            in0 = fmaf(qa.z, ex2_approx(ea), in0);
            in1 = fmaf(qb.z, ex2_approx(eb), in1);
        }
        float inner = in0 + in1;

        // part = sum_k0 D[k1,k0] * pdf(x0; cell[k1,k0])          (row walk)
        float p0 = 0.0f, p1 = 0.0f;
        #pragma unroll
        for (int k0 = 0; k0 < KDIM; k0 += 2) {
            float4 qa = Q[k1 * KDIM + k0];
            float4 qb = Q[k1 * KDIM + k0 + 1];
            float da = x.x - qa.x;
            float db = x.x - qb.x;
            float ea = (qa.y * da) * da;
            float eb = (qb.y * db) * db;
            p0 = fmaf(qa.w, ex2_approx(ea), p0);
            p1 = fmaf(qb.w, ex2_approx(eb), p1);
        }
        float part = p0 + p1;

        acc = fmaf(inner, part, acc);
    }

    out[n] = logf(acc);
}

extern "C" void kernel_launch(void* const* d_in, const int* in_sizes, int n_in,
                              void* d_out, int out_size)
{
    const float* X     = (const float*)d_in[0];
    const float* Wk0   = (const float*)d_in[1];
    const float* Wk1k0 = (const float*)d_in[2];
    const float* Wk2k1 = (const float*)d_in[3];
    const float* mu    = (const float*)d_in[4];
    const float* sigma = (const float*)d_in[5];
    float* out = (float*)d_out;

    int N = out_size;  // one likelihood per sample
    int grid = (N + NTHREADS - 1) / NTHREADS;
    ttg2d_kernel<<<grid, NTHREADS>>>(X, Wk0, Wk1k0, Wk2k1, mu, sigma, out, N);
}